// round 7
// baseline (speedup 1.0000x reference)
#include <cuda_runtime.h>
#include <cuda_fp16.h>
#include <math.h>
#include <stdint.h>

#define BATCH   32
#define SEQ     4096
#define C_IN    7
#define NF      35
#define D_MODEL 512
#define WINDOW  24
#define KDIM    105          // 35 * 3
#define KP      112          // K padded: 7 k16 steps
#define LDH     120          // fp16 leading dim (240B rows, bank-perfect)

// fp32 feature buffer with circular halo rows: P[b][r][i], r in [0,4098),
// P[r] = feats[r-1], P[0] = feats[4095], P[4097] = feats[0].
// A-row for output s = 112 contiguous floats at P + s*35 (cols >=105 hit
// finite neighbor data, annihilated by zero-padded W).
#define PBSTRIDE (4098 * 35 + 2)     // 143432 (16B-aligned per batch)
__device__ __align__(16) float g_P[(size_t)BATCH * PBSTRIDE + 4096];
// W: kappa-major (kappa = kk*35 + i), zero-padded cols 105..119, fp16.
__device__ __align__(16) __half g_Wh[D_MODEL * LDH];

// ---------------------------------------------------------------------------
// Phase 1 (fused): rolling stats -> g_P, plus W reorder/pad -> g_Wh.
// ---------------------------------------------------------------------------
#define P1_TS 256
#define WPREP_BLOCKS ((D_MODEL * LDH) / P1_TS)   // 240

__global__ __launch_bounds__(P1_TS) void stats_kernel(const float* __restrict__ x,
                                                      const float* __restrict__ Wg) {
    const int tid = threadIdx.x;

    if (blockIdx.y == BATCH) {
        int idx = blockIdx.x * P1_TS + tid;
        int n = idx / LDH, k = idx - n * LDH;
        float v = 0.0f;
        if (k < KDIM) v = Wg[(size_t)n * KDIM + (k % NF) * 3 + (k / NF)];
        g_Wh[idx] = __float2half(v);
        return;
    }
    if (blockIdx.x >= SEQ / P1_TS) return;

    __shared__ float sx[(P1_TS + WINDOW - 1) * C_IN];
    const int b   = blockIdx.y;
    const int s0  = blockIdx.x * P1_TS;
    const float* xb = x + (size_t)b * SEQ * C_IN;

    for (int idx = tid; idx < (P1_TS + WINDOW - 1) * C_IN; idx += P1_TS) {
        int sg = s0 - (WINDOW - 1) + idx / C_IN;
        int c  = idx % C_IN;
        if (sg < 0) sg = 0;
        sx[idx] = xb[(size_t)sg * C_IN + c];
    }
    __syncthreads();

    const int s = s0 + tid;
    float* Pb = g_P + (size_t)b * PBSTRIDE;
    float f[NF];

    #pragma unroll
    for (int c = 0; c < C_IN; c++) {
        float sum = 0.0f, mx = -3.0e38f, mn = 3.0e38f;
        #pragma unroll
        for (int t = 0; t < WINDOW; t++) {
            float v = sx[(tid + t) * C_IN + c];
            sum += v; mx = fmaxf(mx, v); mn = fminf(mn, v);
        }
        float mean = sum * (1.0f / WINDOW);
        float s2 = 0.0f;
        #pragma unroll
        for (int t = 0; t < WINDOW; t++) {
            float d = sx[(tid + t) * C_IN + c] - mean;
            s2 += d * d;
        }
        f[c]      = sx[(tid + WINDOW - 1) * C_IN + c];
        f[7 + c]  = mean;
        f[14 + c] = mx;
        f[21 + c] = mn;
        f[28 + c] = sqrtf(s2 * (1.0f / (WINDOW - 1)) + 1e-12f);
    }

    float* dst = Pb + (size_t)(s + 1) * NF;
    #pragma unroll
    for (int i = 0; i < NF; i++) dst[i] = f[i];
    if (s == SEQ - 1) {
        #pragma unroll
        for (int i = 0; i < NF; i++) Pb[i] = f[i];
    }
    if (s == 0) {
        #pragma unroll
        for (int i = 0; i < NF; i++) Pb[(size_t)(SEQ + 1) * NF + i] = f[i];
    }
}

// ---------------------------------------------------------------------------
// Phase 2: fp16 mma.sync GEMM.  f16 accumulate chained across 2 k-steps,
// fp32 spill per pair.  CTA 128x128, 8 warps (2M x 4N), warp 64x32.
// ---------------------------------------------------------------------------
#define BM 128
#define BN 128
#define CTH 256
#define SMEMB (BM * LDH * 2 + BN * LDH * 2 + BN * 4)   // 61952 bytes

__device__ __forceinline__ uint32_t smem_u32(const void* p) {
    uint32_t a;
    asm("{ .reg .u64 t; cvta.to.shared.u64 t, %1; cvt.u32.u64 %0, t; }" : "=r"(a) : "l"(p));
    return a;
}

__global__ __launch_bounds__(CTH, 2) void mma_kernel(const float* __restrict__ bias,
                                                     float* __restrict__ out) {
    extern __shared__ char smem[];
    __half* sA    = (__half*)smem;                       // [BM][LDH]
    __half* sB    = (__half*)(smem + BM * LDH * 2);      // [BN][LDH]
    float*  sBias = (float*)(smem + (BM + BN) * LDH * 2);

    const int tid = threadIdx.x;
    const int b   = blockIdx.x >> 5;          // 32 m-tiles per batch
    const int s0  = (blockIdx.x & 31) * BM;
    const int n0  = blockIdx.y * BN;

    // ---- build A: sliding 112-float windows of g_P, fp32 -> fp16 ----
    const float* Pc = g_P + (size_t)b * PBSTRIDE + (size_t)s0 * NF;
    for (int e = tid; e < BM * KP; e += CTH) {
        int m = e / KP, c = e - m * KP;
        sA[m * LDH + c] = __float2half(Pc[m * NF + c]);
    }
    // ---- build B: contiguous copy of pre-reordered fp16 W tile ----
    {
        const uint4* src = (const uint4*)(g_Wh + (size_t)n0 * LDH);
        uint4* dst = (uint4*)sB;
        for (int i = tid; i < BN * LDH * 2 / 16; i += CTH) dst[i] = src[i];
    }
    if (tid < BN) sBias[tid] = bias[n0 + tid];
    __syncthreads();

    const int lane = tid & 31, w = tid >> 5;
    const int g = lane >> 2, q = lane & 3;
    const int mw = (w & 1) * 64;              // 2 warps along M
    const int nw = (w >> 1) * 32;             // 4 warps along N

    const uint32_t saBase = smem_u32(sA);
    const uint32_t sbBase = smem_u32(sB);
    // A ldmatrix lane address (byte): row = mw + lane&15, col-half = (lane>>4)*8
    const uint32_t aAddr = saBase +
        2u * ((uint32_t)(mw + (lane & 15)) * LDH + ((lane >> 4) << 3));
    // B ldmatrix.x4 lane address: tile t = lane>>3 covers
    //   n-rows (t>>1)*8 .. +7 of the n-set, k-half (t&1)*8
    const uint32_t bt = lane >> 3, bj = lane & 7;
    const uint32_t bAddr = sbBase +
        2u * ((uint32_t)(nw + ((bt >> 1) << 3) + bj) * LDH + ((bt & 1) << 3));

    float acc[4][4][4];
    #pragma unroll
    for (int mi = 0; mi < 4; mi++)
        #pragma unroll
        for (int ni = 0; ni < 4; ni++)
            #pragma unroll
            for (int t = 0; t < 4; t++) acc[mi][ni][t] = 0.0f;

    // 4 groups of k-steps: (0,1) (2,3) (4,5) (6)
    #pragma unroll
    for (int grp = 0; grp < 4; grp++) {
        const int nsteps = (grp < 3) ? 2 : 1;

        // B fragments for both k-steps of this group (ldmatrix.x4: 2 per step)
        uint32_t bf[2][4][2];
        #pragma unroll
        for (int st = 0; st < nsteps; st++) {
            const uint32_t kOff = (uint32_t)(grp * 2 + st) * 32;   // bytes: k0*2
            #pragma unroll
            for (int nset = 0; nset < 2; nset++) {
                uint32_t ba = bAddr + kOff + (uint32_t)(nset * 16 * LDH * 2);
                asm volatile(
                    "ldmatrix.sync.aligned.m8n8.x4.shared.b16 {%0,%1,%2,%3}, [%4];"
                    : "=r"(bf[st][2 * nset][0]),     "=r"(bf[st][2 * nset][1]),
                      "=r"(bf[st][2 * nset + 1][0]), "=r"(bf[st][2 * nset + 1][1])
                    : "r"(ba));
            }
        }

        #pragma unroll
        for (int mi = 0; mi < 4; mi++) {
            uint32_t af[2][4];
            #pragma unroll
            for (int st = 0; st < nsteps; st++) {
                uint32_t aa = aAddr +
                    (uint32_t)(2 * (mi * 16 * LDH + (grp * 2 + st) * 16));
                asm volatile(
                    "ldmatrix.sync.aligned.m8n8.x4.shared.b16 {%0,%1,%2,%3}, [%4];"
                    : "=r"(af[st][0]), "=r"(af[st][1]),
                      "=r"(af[st][2]), "=r"(af[st][3]) : "r"(aa));
            }

            uint32_t d[4][2];
            // step 0: C = 0
            #pragma unroll
            for (int ni = 0; ni < 4; ni++)
                asm volatile(
                    "mma.sync.aligned.m16n8k16.row.col.f16.f16.f16.f16 "
                    "{%0,%1}, {%2,%3,%4,%5}, {%6,%7}, {%8,%8};"
                    : "=r"(d[ni][0]), "=r"(d[ni][1])
                    : "r"(af[0][0]), "r"(af[0][1]), "r"(af[0][2]), "r"(af[0][3]),
                      "r"(bf[0][ni][0]), "r"(bf[0][ni][1]), "r"(0u));
            // step 1: C = d (f16 chain)
            if (nsteps == 2) {
                #pragma unroll
                for (int ni = 0; ni < 4; ni++)
                    asm volatile(
                        "mma.sync.aligned.m16n8k16.row.col.f16.f16.f16.f16 "
                        "{%0,%1}, {%2,%3,%4,%5}, {%6,%7}, {%0,%1};"
                        : "+r"(d[ni][0]), "+r"(d[ni][1])
                        : "r"(af[1][0]), "r"(af[1][1]), "r"(af[1][2]), "r"(af[1][3]),
                          "r"(bf[1][ni][0]), "r"(bf[1][ni][1]));
            }
            // spill to fp32 (once per k-step pair)
            #pragma unroll
            for (int ni = 0; ni < 4; ni++) {
                float2 lo = __half22float2(*(__half2*)&d[ni][0]);
                float2 hi = __half22float2(*(__half2*)&d[ni][1]);
                acc[mi][ni][0] += lo.x;
                acc[mi][ni][1] += lo.y;
                acc[mi][ni][2] += hi.x;
                acc[mi][ni][3] += hi.y;
            }
        }
    }

    // ---- epilogue: bias + float2 stores ----
    #pragma unroll
    for (int mi = 0; mi < 4; mi++) {
        #pragma unroll
        for (int ni = 0; ni < 4; ni++) {
            const int colL = nw + ni * 8 + 2 * q;
            const float bx = sBias[colL], by = sBias[colL + 1];
            const size_t r1 = (size_t)b * SEQ + s0 + mw + mi * 16 + g;
            float* p = out + r1 * D_MODEL + n0 + colL;
            float2 v0 = { acc[mi][ni][0] + bx, acc[mi][ni][1] + by };
            float2 v1 = { acc[mi][ni][2] + bx, acc[mi][ni][3] + by };
            *(float2*)p = v0;
            *(float2*)(p + 8 * D_MODEL) = v1;
        }
    }
}

// ---------------------------------------------------------------------------
extern "C" void kernel_launch(void* const* d_in, const int* in_sizes, int n_in,
                              void* d_out, int out_size) {
    const float* x = nullptr; const float* Wg = nullptr; const float* bias = nullptr;
    for (int i = 0; i < n_in; i++) {
        if (in_sizes[i] == BATCH * SEQ * C_IN)   x    = (const float*)d_in[i];
        else if (in_sizes[i] == D_MODEL * KDIM)  Wg   = (const float*)d_in[i];
        else if (in_sizes[i] == D_MODEL)         bias = (const float*)d_in[i];
        // x_mark (BATCH*SEQ*4) unused by the reference math
    }
    float* out = (float*)d_out;

    dim3 g1(WPREP_BLOCKS, BATCH + 1);
    stats_kernel<<<g1, P1_TS>>>(x, Wg);

    cudaFuncSetAttribute(mma_kernel, cudaFuncAttributeMaxDynamicSharedMemorySize, SMEMB);
    dim3 g2((BATCH * SEQ) / BM, D_MODEL / BN, 1);
    mma_kernel<<<g2, CTH, SMEMB>>>(bias, out);
}

// round 8
// speedup vs baseline: 1.3775x; 1.3775x over previous
#include <cuda_runtime.h>
#include <cuda_fp16.h>
#include <math.h>
#include <stdint.h>

#define BATCH   32
#define SEQ     4096
#define C_IN    7
#define NF      35
#define D_MODEL 512
#define WINDOW  24
#define KDIM    105          // 35 * 3
#define KP      112          // K padded: 7 k16 steps
#define LDH     120          // fp16 leading dim (240B rows, bank-perfect)

// fp32 feature buffer with circular halo rows: P[b][r][i], r in [0,4098),
// P[r] = feats[r-1], P[0] = feats[4095], P[4097] = feats[0].
// A-row for output s = 112 contiguous floats at P + s*35 (cols >=105 hit
// finite neighbor data, annihilated by zero-padded W).
#define PBSTRIDE (4098 * 35 + 2)     // 143432 (16B-aligned per batch)
__device__ __align__(16) float g_P[(size_t)BATCH * PBSTRIDE + 4096];
// W: kappa-major (kappa = kk*35 + i), zero-padded cols 105..119, fp16.
__device__ __align__(16) __half g_Wh[D_MODEL * LDH];

// ---------------------------------------------------------------------------
// Phase 1 (fused): rolling stats -> g_P (coalesced via smem staging),
// plus W reorder/pad -> g_Wh on the extra y-slice.
// ---------------------------------------------------------------------------
#define P1_TS 256
#define WPREP_BLOCKS ((D_MODEL * LDH) / P1_TS)   // 240

__global__ __launch_bounds__(P1_TS) void stats_kernel(const float* __restrict__ x,
                                                      const float* __restrict__ Wg) {
    const int tid = threadIdx.x;

    if (blockIdx.y == BATCH) {
        int idx = blockIdx.x * P1_TS + tid;
        int n = idx / LDH, k = idx - n * LDH;
        float v = 0.0f;
        if (k < KDIM) v = Wg[(size_t)n * KDIM + (k % NF) * 3 + (k / NF)];
        g_Wh[idx] = __float2half(v);
        return;
    }
    if (blockIdx.x >= SEQ / P1_TS) return;

    __shared__ float sx[(P1_TS + WINDOW - 1) * C_IN];   //  7812 B
    __shared__ float stg[P1_TS * NF];                   // 35840 B

    const int b   = blockIdx.y;
    const int s0  = blockIdx.x * P1_TS;
    const float* xb = x + (size_t)b * SEQ * C_IN;

    for (int idx = tid; idx < (P1_TS + WINDOW - 1) * C_IN; idx += P1_TS) {
        int sg = s0 - (WINDOW - 1) + idx / C_IN;
        int c  = idx % C_IN;
        if (sg < 0) sg = 0;
        sx[idx] = xb[(size_t)sg * C_IN + c];
    }
    __syncthreads();

    const int s = s0 + tid;
    float* Pb = g_P + (size_t)b * PBSTRIDE;
    float f[NF];

    #pragma unroll
    for (int c = 0; c < C_IN; c++) {
        float sum = 0.0f, mx = -3.0e38f, mn = 3.0e38f;
        #pragma unroll
        for (int t = 0; t < WINDOW; t++) {
            float v = sx[(tid + t) * C_IN + c];
            sum += v; mx = fmaxf(mx, v); mn = fminf(mn, v);
        }
        float mean = sum * (1.0f / WINDOW);
        float s2 = 0.0f;
        #pragma unroll
        for (int t = 0; t < WINDOW; t++) {
            float d = sx[(tid + t) * C_IN + c] - mean;
            s2 += d * d;
        }
        f[c]      = sx[(tid + WINDOW - 1) * C_IN + c];
        f[7 + c]  = mean;
        f[14 + c] = mx;
        f[21 + c] = mn;
        f[28 + c] = sqrtf(s2 * (1.0f / (WINDOW - 1)) + 1e-12f);
    }

    // stage (stride 35 -> conflict-free: gcd(35,32)=1), then coalesced STG
    #pragma unroll
    for (int i = 0; i < NF; i++) stg[tid * NF + i] = f[i];

    // circular halo rows (tiny, direct)
    if (s == SEQ - 1) {
        #pragma unroll
        for (int i = 0; i < NF; i++) Pb[i] = f[i];
    }
    if (s == 0) {
        #pragma unroll
        for (int i = 0; i < NF; i++) Pb[(size_t)(SEQ + 1) * NF + i] = f[i];
    }
    __syncthreads();

    float* dst = Pb + (size_t)(s0 + 1) * NF;
    for (int idx = tid; idx < P1_TS * NF; idx += P1_TS)
        dst[idx] = stg[idx];
}

// ---------------------------------------------------------------------------
// Phase 2: fp16 mma.sync GEMM, full fp16 accumulation chain (K=112 in f16 C),
// CTA 128x128, 8 warps (2M x 4N), warp 64x32, 3 CTAs/SM.
// ---------------------------------------------------------------------------
#define BM 128
#define BN 128
#define CTH 256
#define SMEMB (BM * LDH * 2 + BN * LDH * 2 + BN * 4)   // 61952 bytes

__device__ __forceinline__ uint32_t smem_u32(const void* p) {
    uint32_t a;
    asm("{ .reg .u64 t; cvta.to.shared.u64 t, %1; cvt.u32.u64 %0, t; }" : "=r"(a) : "l"(p));
    return a;
}

__global__ __launch_bounds__(CTH, 3) void mma_kernel(const float* __restrict__ bias,
                                                     float* __restrict__ out) {
    extern __shared__ char smem[];
    __half* sA    = (__half*)smem;                       // [BM][LDH]
    __half* sB    = (__half*)(smem + BM * LDH * 2);      // [BN][LDH]
    float*  sBias = (float*)(smem + (BM + BN) * LDH * 2);

    const int tid = threadIdx.x;
    const int b   = blockIdx.x >> 5;          // 32 m-tiles per batch
    const int s0  = (blockIdx.x & 31) * BM;
    const int n0  = blockIdx.y * BN;

    // ---- build A: sliding 112-float windows of g_P, fp32 -> fp16 ----
    const float* Pc = g_P + (size_t)b * PBSTRIDE + (size_t)s0 * NF;
    for (int e = tid; e < BM * KP; e += CTH) {
        int m = e / KP, c = e - m * KP;
        sA[m * LDH + c] = __float2half(Pc[m * NF + c]);
    }
    // ---- build B: contiguous copy of pre-reordered fp16 W tile ----
    {
        const uint4* src = (const uint4*)(g_Wh + (size_t)n0 * LDH);
        uint4* dst = (uint4*)sB;
        for (int i = tid; i < BN * LDH * 2 / 16; i += CTH) dst[i] = src[i];
    }
    if (tid < BN) sBias[tid] = bias[n0 + tid];
    __syncthreads();

    const int lane = tid & 31, w = tid >> 5;
    const int g = lane >> 2, q = lane & 3;
    const int mw = (w & 1) * 64;              // 2 warps along M
    const int nw = (w >> 1) * 32;             // 4 warps along N

    const uint32_t saBase = smem_u32(sA);
    const uint32_t sbBase = smem_u32(sB);
    const uint32_t aAddr = saBase +
        2u * ((uint32_t)(mw + (lane & 15)) * LDH + ((lane >> 4) << 3));
    const uint32_t bt = lane >> 3, bj = lane & 7;
    const uint32_t bAddr = sbBase +
        2u * ((uint32_t)(nw + ((bt >> 1) << 3) + bj) * LDH + ((bt & 1) << 3));

    // persistent fp16x2 accumulators
    uint32_t d[4][4][2];
    #pragma unroll
    for (int mi = 0; mi < 4; mi++)
        #pragma unroll
        for (int ni = 0; ni < 4; ni++)
            d[mi][ni][0] = d[mi][ni][1] = 0u;

    // 4 groups of k-steps: (0,1) (2,3) (4,5) (6)
    #pragma unroll
    for (int grp = 0; grp < 4; grp++) {
        const int nsteps = (grp < 3) ? 2 : 1;

        uint32_t bf[2][4][2];
        #pragma unroll
        for (int st = 0; st < nsteps; st++) {
            const uint32_t kOff = (uint32_t)(grp * 2 + st) * 32;   // bytes
            #pragma unroll
            for (int nset = 0; nset < 2; nset++) {
                uint32_t ba = bAddr + kOff + (uint32_t)(nset * 16 * LDH * 2);
                asm volatile(
                    "ldmatrix.sync.aligned.m8n8.x4.shared.b16 {%0,%1,%2,%3}, [%4];"
                    : "=r"(bf[st][2 * nset][0]),     "=r"(bf[st][2 * nset][1]),
                      "=r"(bf[st][2 * nset + 1][0]), "=r"(bf[st][2 * nset + 1][1])
                    : "r"(ba));
            }
        }

        #pragma unroll
        for (int mi = 0; mi < 4; mi++) {
            uint32_t af[2][4];
            #pragma unroll
            for (int st = 0; st < nsteps; st++) {
                uint32_t aa = aAddr +
                    (uint32_t)(2 * (mi * 16 * LDH + (grp * 2 + st) * 16));
                asm volatile(
                    "ldmatrix.sync.aligned.m8n8.x4.shared.b16 {%0,%1,%2,%3}, [%4];"
                    : "=r"(af[st][0]), "=r"(af[st][1]),
                      "=r"(af[st][2]), "=r"(af[st][3]) : "r"(aa));
            }
            #pragma unroll
            for (int st = 0; st < nsteps; st++) {
                #pragma unroll
                for (int ni = 0; ni < 4; ni++)
                    asm volatile(
                        "mma.sync.aligned.m16n8k16.row.col.f16.f16.f16.f16 "
                        "{%0,%1}, {%2,%3,%4,%5}, {%6,%7}, {%0,%1};"
                        : "+r"(d[mi][ni][0]), "+r"(d[mi][ni][1])
                        : "r"(af[st][0]), "r"(af[st][1]), "r"(af[st][2]), "r"(af[st][3]),
                          "r"(bf[st][ni][0]), "r"(bf[st][ni][1]));
            }
        }
    }

    // ---- epilogue: f16 -> f32, bias, float2 stores ----
    #pragma unroll
    for (int mi = 0; mi < 4; mi++) {
        #pragma unroll
        for (int ni = 0; ni < 4; ni++) {
            const int colL = nw + ni * 8 + 2 * q;
            const float bx = sBias[colL], by = sBias[colL + 1];
            const size_t r1 = (size_t)b * SEQ + s0 + mw + mi * 16 + g;
            float* p = out + r1 * D_MODEL + n0 + colL;
            float2 lo = __half22float2(*(__half2*)&d[mi][ni][0]);
            float2 hi = __half22float2(*(__half2*)&d[mi][ni][1]);
            float2 v0 = { lo.x + bx, lo.y + by };
            float2 v1 = { hi.x + bx, hi.y + by };
            *(float2*)p = v0;
            *(float2*)(p + 8 * D_MODEL) = v1;
        }
    }
}

// ---------------------------------------------------------------------------
extern "C" void kernel_launch(void* const* d_in, const int* in_sizes, int n_in,
                              void* d_out, int out_size) {
    const float* x = nullptr; const float* Wg = nullptr; const float* bias = nullptr;
    for (int i = 0; i < n_in; i++) {
        if (in_sizes[i] == BATCH * SEQ * C_IN)   x    = (const float*)d_in[i];
        else if (in_sizes[i] == D_MODEL * KDIM)  Wg   = (const float*)d_in[i];
        else if (in_sizes[i] == D_MODEL)         bias = (const float*)d_in[i];
        // x_mark (BATCH*SEQ*4) unused by the reference math
    }
    float* out = (float*)d_out;

    dim3 g1(WPREP_BLOCKS, BATCH + 1);
    stats_kernel<<<g1, P1_TS>>>(x, Wg);

    cudaFuncSetAttribute(mma_kernel, cudaFuncAttributeMaxDynamicSharedMemorySize, SMEMB);
    dim3 g2((BATCH * SEQ) / BM, D_MODEL / BN, 1);
    mma_kernel<<<g2, CTH, SMEMB>>>(bias, out);
}

// round 9
// speedup vs baseline: 1.4482x; 1.0513x over previous
#include <cuda_runtime.h>
#include <cuda_fp16.h>
#include <math.h>
#include <stdint.h>

#define BATCH   32
#define SEQ     4096
#define C_IN    7
#define NF      35
#define D_MODEL 512
#define WINDOW  24
#define KDIM    105          // 35 * 3
#define KP      112          // K padded: 7 k16 steps
#define LDH     120          // fp16 leading dim (240B rows, bank-perfect)

// fp32 feature buffer with circular halo rows: P[b][r][i], r in [0,4098),
// P[r] = feats[r-1], P[0] = feats[4095], P[4097] = feats[0].
// A-row for output s = 112 contiguous floats at P + s*35 (cols >=105 hit
// finite neighbor data, annihilated by zero-padded W).
#define PBSTRIDE (4098 * 35 + 2)     // 143432 (16B-aligned per batch)
__device__ __align__(16) float g_P[(size_t)BATCH * PBSTRIDE + 4096];
// W: kappa-major (kappa = kk*35 + i), zero-padded cols 105..119, fp16.
__device__ __align__(16) __half g_Wh[D_MODEL * LDH];

// ---------------------------------------------------------------------------
// Phase 1 (fused): rolling stats -> g_P (coalesced via smem staging),
// plus W reorder/pad -> g_Wh on the extra y-slice.
// ---------------------------------------------------------------------------
#define P1_TS 256
#define WPREP_BLOCKS ((D_MODEL * LDH) / P1_TS)   // 240

__global__ __launch_bounds__(P1_TS) void stats_kernel(const float* __restrict__ x,
                                                      const float* __restrict__ Wg) {
    const int tid = threadIdx.x;

    if (blockIdx.y == BATCH) {
        int idx = blockIdx.x * P1_TS + tid;
        int n = idx / LDH, k = idx - n * LDH;
        float v = 0.0f;
        if (k < KDIM) v = Wg[(size_t)n * KDIM + (k % NF) * 3 + (k / NF)];
        g_Wh[idx] = __float2half(v);
        return;
    }
    if (blockIdx.x >= SEQ / P1_TS) return;

    __shared__ float sx[(P1_TS + WINDOW - 1) * C_IN];
    __shared__ float stg[P1_TS * NF];

    const int b   = blockIdx.y;
    const int s0  = blockIdx.x * P1_TS;
    const float* xb = x + (size_t)b * SEQ * C_IN;

    for (int idx = tid; idx < (P1_TS + WINDOW - 1) * C_IN; idx += P1_TS) {
        int sg = s0 - (WINDOW - 1) + idx / C_IN;
        int c  = idx % C_IN;
        if (sg < 0) sg = 0;
        sx[idx] = xb[(size_t)sg * C_IN + c];
    }
    __syncthreads();

    const int s = s0 + tid;
    float* Pb = g_P + (size_t)b * PBSTRIDE;
    float f[NF];

    #pragma unroll
    for (int c = 0; c < C_IN; c++) {
        float sum = 0.0f, mx = -3.0e38f, mn = 3.0e38f;
        #pragma unroll
        for (int t = 0; t < WINDOW; t++) {
            float v = sx[(tid + t) * C_IN + c];
            sum += v; mx = fmaxf(mx, v); mn = fminf(mn, v);
        }
        float mean = sum * (1.0f / WINDOW);
        float s2 = 0.0f;
        #pragma unroll
        for (int t = 0; t < WINDOW; t++) {
            float d = sx[(tid + t) * C_IN + c] - mean;
            s2 += d * d;
        }
        f[c]      = sx[(tid + WINDOW - 1) * C_IN + c];
        f[7 + c]  = mean;
        f[14 + c] = mx;
        f[21 + c] = mn;
        f[28 + c] = sqrtf(s2 * (1.0f / (WINDOW - 1)) + 1e-12f);
    }

    #pragma unroll
    for (int i = 0; i < NF; i++) stg[tid * NF + i] = f[i];

    if (s == SEQ - 1) {
        #pragma unroll
        for (int i = 0; i < NF; i++) Pb[i] = f[i];
    }
    if (s == 0) {
        #pragma unroll
        for (int i = 0; i < NF; i++) Pb[(size_t)(SEQ + 1) * NF + i] = f[i];
    }
    __syncthreads();

    float* dst = Pb + (size_t)(s0 + 1) * NF;
    for (int idx = tid; idx < P1_TS * NF; idx += P1_TS)
        dst[idx] = stg[idx];
}

// ---------------------------------------------------------------------------
// Phase 2: fp16 mma.sync GEMM, full fp16 accumulation chain.
// CTA 64(M) x 128(N), 8 warps (2M x 4N), warp 32x32, 4 CTAs/SM.
// ---------------------------------------------------------------------------
#define BM 64
#define BN 128
#define CTH 256
#define SMEMB (BM * LDH * 2 + BN * LDH * 2 + BN * 4)   // 46592 bytes

__device__ __forceinline__ uint32_t smem_u32(const void* p) {
    uint32_t a;
    asm("{ .reg .u64 t; cvta.to.shared.u64 t, %1; cvt.u32.u64 %0, t; }" : "=r"(a) : "l"(p));
    return a;
}

__global__ __launch_bounds__(CTH, 4) void mma_kernel(const float* __restrict__ bias,
                                                     float* __restrict__ out) {
    extern __shared__ char smem[];
    __half* sA    = (__half*)smem;                       // [BM][LDH]
    __half* sB    = (__half*)(smem + BM * LDH * 2);      // [BN][LDH]
    float*  sBias = (float*)(smem + (BM + BN) * LDH * 2);

    const int tid = threadIdx.x;
    const int b   = blockIdx.x >> 6;          // 64 m-tiles per batch
    const int s0  = (blockIdx.x & 63) * BM;
    const int n0  = blockIdx.y * BN;

    // ---- build A: sliding 112-float windows of g_P, fp32 -> fp16 ----
    const float* Pc = g_P + (size_t)b * PBSTRIDE + (size_t)s0 * NF;
    for (int e = tid; e < BM * KP; e += CTH) {
        int m = e / KP, c = e - m * KP;
        sA[m * LDH + c] = __float2half(Pc[m * NF + c]);
    }
    // ---- build B: contiguous copy of pre-reordered fp16 W tile ----
    {
        const uint4* src = (const uint4*)(g_Wh + (size_t)n0 * LDH);
        uint4* dst = (uint4*)sB;
        for (int i = tid; i < BN * LDH * 2 / 16; i += CTH) dst[i] = src[i];
    }
    if (tid < BN) sBias[tid] = bias[n0 + tid];
    __syncthreads();

    const int lane = tid & 31, w = tid >> 5;
    const int g = lane >> 2, q = lane & 3;
    const int mw = (w & 1) * 32;              // 2 warps along M (32 rows each)
    const int nw = (w >> 1) * 32;             // 4 warps along N

    const uint32_t saBase = smem_u32(sA);
    const uint32_t sbBase = smem_u32(sB);
    const uint32_t aAddr = saBase +
        2u * ((uint32_t)(mw + (lane & 15)) * LDH + ((lane >> 4) << 3));
    const uint32_t bt = lane >> 3, bj = lane & 7;
    const uint32_t bAddr = sbBase +
        2u * ((uint32_t)(nw + ((bt >> 1) << 3) + bj) * LDH + ((bt & 1) << 3));

    // persistent fp16x2 accumulators: 2 m-frags x 4 n-frags
    uint32_t d[2][4][2];
    #pragma unroll
    for (int mi = 0; mi < 2; mi++)
        #pragma unroll
        for (int ni = 0; ni < 4; ni++)
            d[mi][ni][0] = d[mi][ni][1] = 0u;

    #pragma unroll
    for (int ks = 0; ks < 7; ks++) {
        const uint32_t kOff = (uint32_t)ks * 32;   // bytes (k0 * 2)

        uint32_t bf[4][2];
        #pragma unroll
        for (int nset = 0; nset < 2; nset++) {
            uint32_t ba = bAddr + kOff + (uint32_t)(nset * 16 * LDH * 2);
            asm volatile(
                "ldmatrix.sync.aligned.m8n8.x4.shared.b16 {%0,%1,%2,%3}, [%4];"
                : "=r"(bf[2 * nset][0]),     "=r"(bf[2 * nset][1]),
                  "=r"(bf[2 * nset + 1][0]), "=r"(bf[2 * nset + 1][1])
                : "r"(ba));
        }

        #pragma unroll
        for (int mi = 0; mi < 2; mi++) {
            uint32_t af[4];
            uint32_t aa = aAddr + (uint32_t)(2 * (mi * 16 * LDH)) + kOff;
            asm volatile(
                "ldmatrix.sync.aligned.m8n8.x4.shared.b16 {%0,%1,%2,%3}, [%4];"
                : "=r"(af[0]), "=r"(af[1]), "=r"(af[2]), "=r"(af[3]) : "r"(aa));
            #pragma unroll
            for (int ni = 0; ni < 4; ni++)
                asm volatile(
                    "mma.sync.aligned.m16n8k16.row.col.f16.f16.f16.f16 "
                    "{%0,%1}, {%2,%3,%4,%5}, {%6,%7}, {%0,%1};"
                    : "+r"(d[mi][ni][0]), "+r"(d[mi][ni][1])
                    : "r"(af[0]), "r"(af[1]), "r"(af[2]), "r"(af[3]),
                      "r"(bf[ni][0]), "r"(bf[ni][1]));
        }
    }

    // ---- epilogue: f16 -> f32, bias, float2 stores ----
    #pragma unroll
    for (int mi = 0; mi < 2; mi++) {
        #pragma unroll
        for (int ni = 0; ni < 4; ni++) {
            const int colL = nw + ni * 8 + 2 * q;
            const float bx = sBias[colL], by = sBias[colL + 1];
            const size_t r1 = (size_t)b * SEQ + s0 + mw + mi * 16 + g;
            float* p = out + r1 * D_MODEL + n0 + colL;
            float2 lo = __half22float2(*(__half2*)&d[mi][ni][0]);
            float2 hi = __half22float2(*(__half2*)&d[mi][ni][1]);
            float2 v0 = { lo.x + bx, lo.y + by };
            float2 v1 = { hi.x + bx, hi.y + by };
            *(float2*)p = v0;
            *(float2*)(p + 8 * D_MODEL) = v1;
        }
    }
}

// ---------------------------------------------------------------------------
extern "C" void kernel_launch(void* const* d_in, const int* in_sizes, int n_in,
                              void* d_out, int out_size) {
    const float* x = nullptr; const float* Wg = nullptr; const float* bias = nullptr;
    for (int i = 0; i < n_in; i++) {
        if (in_sizes[i] == BATCH * SEQ * C_IN)   x    = (const float*)d_in[i];
        else if (in_sizes[i] == D_MODEL * KDIM)  Wg   = (const float*)d_in[i];
        else if (in_sizes[i] == D_MODEL)         bias = (const float*)d_in[i];
        // x_mark (BATCH*SEQ*4) unused by the reference math
    }
    float* out = (float*)d_out;

    dim3 g1(WPREP_BLOCKS, BATCH + 1);
    stats_kernel<<<g1, P1_TS>>>(x, Wg);

    cudaFuncSetAttribute(mma_kernel, cudaFuncAttributeMaxDynamicSharedMemorySize, SMEMB);
    dim3 g2((BATCH * SEQ) / BM, D_MODEL / BN, 1);
    mma_kernel<<<g2, CTH, SMEMB>>>(bias, out);
}

// round 10
// speedup vs baseline: 1.5934x; 1.1003x over previous
#include <cuda_runtime.h>
#include <cuda_fp16.h>
#include <math.h>
#include <stdint.h>

#define BATCH   32
#define SEQ     4096
#define C_IN    7
#define NF      35
#define D_MODEL 512
#define WINDOW  24
#define KDIM    105
#define KP      112          // K padded: 7 k16 steps
#define LDH     120          // halfs per A/W row (240B, ldmatrix bank-clean)
// A row layout: [feats[s-1] @0..34 | feats[s] @36..70 | feats[s+1] @72..106],
// cols 35, 71, 107..119 are zero.  W col = tap*36 + i, zero at gaps.

// Pre-windowed fp16 A: [BATCH*SEQ][LDH]
__device__ __align__(16) __half g_Ah[(size_t)BATCH * SEQ * LDH];
// W reordered/padded fp16: [D_MODEL][LDH]
__device__ __align__(16) __half g_Wh[D_MODEL * LDH];

// ---------------------------------------------------------------------------
// Phase 1 (fused): rolling stats -> windowed fp16 A rows;  W prep on the
// extra y-slice.
// ---------------------------------------------------------------------------
#define P1_TS 256
#define WPREP_BLOCKS ((D_MODEL * LDH) / P1_TS)   // 240
#define SXROWS (P1_TS + WINDOW + 1)              // 281: x rows s0-24 .. s0+256
#define AST_LD 122                               // staging stride (244B, bank-coprime)
#define S1_SMEM (P1_TS * AST_LD * 2 + SXROWS * C_IN * 4)   // 62464 + 7868

__device__ __forceinline__ void stats5(const float* win, int stride, float out[5]) {
    float sum = 0.0f, mx = -3.0e38f, mn = 3.0e38f;
    #pragma unroll
    for (int t = 0; t < WINDOW; t++) {
        float v = win[t * stride];
        sum += v; mx = fmaxf(mx, v); mn = fminf(mn, v);
    }
    float mean = sum * (1.0f / WINDOW);
    float s2 = 0.0f;
    #pragma unroll
    for (int t = 0; t < WINDOW; t++) {
        float d = win[t * stride] - mean;
        s2 += d * d;
    }
    out[0] = win[(WINDOW - 1) * stride];
    out[1] = mean;
    out[2] = mx;
    out[3] = mn;
    out[4] = sqrtf(s2 * (1.0f / (WINDOW - 1)) + 1e-12f);
}

__global__ __launch_bounds__(P1_TS) void stats_kernel(const float* __restrict__ x,
                                                      const float* __restrict__ Wg) {
    const int tid = threadIdx.x;

    if (blockIdx.y == BATCH) {
        // W prep: col = tap*36 + i  ->  W[n][i*3 + tap]; gaps zero
        int idx = blockIdx.x * P1_TS + tid;
        int n = idx / LDH, k = idx - n * LDH;
        int tap = k / 36, i = k - tap * 36;
        float v = 0.0f;
        if (k < 108 && i < NF) v = Wg[(size_t)n * KDIM + i * 3 + tap];
        g_Wh[idx] = __float2half(v);
        return;
    }
    if (blockIdx.x >= SEQ / P1_TS) return;

    extern __shared__ char s1m[];
    __half* ast = (__half*)s1m;                         // [256][AST_LD]
    float*  sx  = (float*)(s1m + P1_TS * AST_LD * 2);   // [SXROWS][C_IN]

    const int b   = blockIdx.y;
    const int s0  = blockIdx.x * P1_TS;
    const float* xb = x + (size_t)b * SEQ * C_IN;

    // x tile: sx row l <-> global sg = s0 - 24 + l (clamped to 0)
    for (int idx = tid; idx < SXROWS * C_IN; idx += P1_TS) {
        int sg = s0 - (WINDOW)+idx / C_IN;   // s0 - 24 + l
        int c  = idx % C_IN;
        if (sg < 0) sg = 0;
        sx[idx] = xb[(size_t)sg * C_IN + c];
    }
    __syncthreads();

    // ---- main positions p = tid in [0, 256): feats -> scatter 3 slices ----
    {
        const int p = tid;
        float f[NF];
        #pragma unroll
        for (int c = 0; c < C_IN; c++) {
            float o[5];
            stats5(&sx[(p + 1) * C_IN + c], C_IN, o);
            f[c] = o[0]; f[7 + c] = o[1]; f[14 + c] = o[2];
            f[21 + c] = o[3]; f[28 + c] = o[4];
        }
        // pack to half2 pairs once
        uint32_t hp[17]; __half last;
        #pragma unroll
        for (int i = 0; i < 17; i++) {
            __half2 h = __floats2half2_rn(f[2 * i], f[2 * i + 1]);
            hp[i] = *(uint32_t*)&h;
        }
        last = __float2half(f[34]);
        // slice0 -> row p+1, slice1 -> row p, slice2 -> row p-1
        #pragma unroll
        for (int sl = 0; sl < 3; sl++) {
            int row = p + 1 - sl;
            if (row >= 0 && row < P1_TS) {
                uint32_t* dst = (uint32_t*)(ast + row * AST_LD + sl * 36);
                #pragma unroll
                for (int i = 0; i < 17; i++) dst[i] = hp[i];
                *((__half*)dst + 34) = last;
            }
        }
    }

    // ---- boundary positions p = -1, 256 (wrapped, direct gmem) ----
    if (tid < 2 * C_IN) {
        const int p = (tid < C_IN) ? -1 : P1_TS;
        const int c = tid % C_IN;
        const int sglob = (s0 + p) & (SEQ - 1);
        float win[WINDOW];
        #pragma unroll
        for (int t = 0; t < WINDOW; t++) {
            int sg = sglob - (WINDOW - 1) + t;
            if (sg < 0) sg = 0;
            win[t] = xb[(size_t)sg * C_IN + c];
        }
        float o[5];
        stats5(win, 1, o);
        // p=-1 -> row 0 slice0; p=256 -> row 255 slice2
        int row = (p < 0) ? 0 : (P1_TS - 1);
        int sl  = (p < 0) ? 0 : 2;
        __half* dst = ast + row * AST_LD + sl * 36;
        dst[c]      = __float2half(o[0]);
        dst[7 + c]  = __float2half(o[1]);
        dst[14 + c] = __float2half(o[2]);
        dst[21 + c] = __float2half(o[3]);
        dst[28 + c] = __float2half(o[4]);
    }
    __syncthreads();

    // ---- coalesced write: 256 rows x 60 uints, masking gap columns ----
    const uint32_t* astu = (const uint32_t*)ast;
    uint32_t* outu = (uint32_t*)g_Ah + ((size_t)b * SEQ + s0) * (LDH / 2);
    for (int idx = tid; idx < P1_TS * (LDH / 2); idx += P1_TS) {
        int m = idx / (LDH / 2), pc = idx - m * (LDH / 2);
        uint32_t v = 0;
        if (pc < 54) {
            v = astu[m * (AST_LD / 2) + pc];
            if (pc == 17 || pc == 35 || pc == 53) v &= 0x0000FFFFu;  // zero hi half
        }
        outu[idx] = v;
    }
}

// ---------------------------------------------------------------------------
// Phase 2: fp16 mma.sync GEMM, full fp16 accumulation chain.
// CTA 64(M) x 128(N), 8 warps (2M x 4N), warp 32x32, 4 CTAs/SM.
// A build = contiguous uint4 copy of pre-windowed g_Ah.
// ---------------------------------------------------------------------------
#define BM 64
#define BN 128
#define CTH 256
#define SMEMB (BM * LDH * 2 + BN * LDH * 2 + BN * 4)   // 46592 bytes

__device__ __forceinline__ uint32_t smem_u32(const void* p) {
    uint32_t a;
    asm("{ .reg .u64 t; cvta.to.shared.u64 t, %1; cvt.u32.u64 %0, t; }" : "=r"(a) : "l"(p));
    return a;
}

__global__ __launch_bounds__(CTH, 4) void mma_kernel(const float* __restrict__ bias,
                                                     float* __restrict__ out) {
    extern __shared__ char smem[];
    __half* sA    = (__half*)smem;                       // [BM][LDH]
    __half* sB    = (__half*)(smem + BM * LDH * 2);      // [BN][LDH]
    float*  sBias = (float*)(smem + (BM + BN) * LDH * 2);

    const int tid = threadIdx.x;
    const int mt  = blockIdx.x;               // global M-tile (row = mt*64)
    const int n0  = blockIdx.y * BN;

    // ---- A: contiguous uint4 copy (15360 B) ----
    {
        const uint4* src = (const uint4*)(g_Ah + (size_t)mt * BM * LDH);
        uint4* dst = (uint4*)sA;
        for (int i = tid; i < BM * LDH * 2 / 16; i += CTH) dst[i] = src[i];
    }
    // ---- B: contiguous uint4 copy of W tile (30720 B) ----
    {
        const uint4* src = (const uint4*)(g_Wh + (size_t)n0 * LDH);
        uint4* dst = (uint4*)sB;
        for (int i = tid; i < BN * LDH * 2 / 16; i += CTH) dst[i] = src[i];
    }
    if (tid < BN) sBias[tid] = bias[n0 + tid];
    __syncthreads();

    const int lane = tid & 31, w = tid >> 5;
    const int g = lane >> 2, q = lane & 3;
    const int mw = (w & 1) * 32;              // 2 warps along M
    const int nw = (w >> 1) * 32;             // 4 warps along N

    const uint32_t saBase = smem_u32(sA);
    const uint32_t sbBase = smem_u32(sB);
    const uint32_t aAddr = saBase +
        2u * ((uint32_t)(mw + (lane & 15)) * LDH + ((lane >> 4) << 3));
    const uint32_t bt = lane >> 3, bj = lane & 7;
    const uint32_t bAddr = sbBase +
        2u * ((uint32_t)(nw + ((bt >> 1) << 3) + bj) * LDH + ((bt & 1) << 3));

    uint32_t d[2][4][2];
    #pragma unroll
    for (int mi = 0; mi < 2; mi++)
        #pragma unroll
        for (int ni = 0; ni < 4; ni++)
            d[mi][ni][0] = d[mi][ni][1] = 0u;

    #pragma unroll
    for (int ks = 0; ks < 7; ks++) {
        const uint32_t kOff = (uint32_t)ks * 32;   // bytes

        uint32_t bf[4][2];
        #pragma unroll
        for (int nset = 0; nset < 2; nset++) {
            uint32_t ba = bAddr + kOff + (uint32_t)(nset * 16 * LDH * 2);
            asm volatile(
                "ldmatrix.sync.aligned.m8n8.x4.shared.b16 {%0,%1,%2,%3}, [%4];"
                : "=r"(bf[2 * nset][0]),     "=r"(bf[2 * nset][1]),
                  "=r"(bf[2 * nset + 1][0]), "=r"(bf[2 * nset + 1][1])
                : "r"(ba));
        }

        #pragma unroll
        for (int mi = 0; mi < 2; mi++) {
            uint32_t af[4];
            uint32_t aa = aAddr + (uint32_t)(2 * (mi * 16 * LDH)) + kOff;
            asm volatile(
                "ldmatrix.sync.aligned.m8n8.x4.shared.b16 {%0,%1,%2,%3}, [%4];"
                : "=r"(af[0]), "=r"(af[1]), "=r"(af[2]), "=r"(af[3]) : "r"(aa));
            #pragma unroll
            for (int ni = 0; ni < 4; ni++)
                asm volatile(
                    "mma.sync.aligned.m16n8k16.row.col.f16.f16.f16.f16 "
                    "{%0,%1}, {%2,%3,%4,%5}, {%6,%7}, {%0,%1};"
                    : "+r"(d[mi][ni][0]), "+r"(d[mi][ni][1])
                    : "r"(af[0]), "r"(af[1]), "r"(af[2]), "r"(af[3]),
                      "r"(bf[ni][0]), "r"(bf[ni][1]));
        }
    }

    // ---- epilogue: f16 -> f32, bias, float2 stores ----
    #pragma unroll
    for (int mi = 0; mi < 2; mi++) {
        #pragma unroll
        for (int ni = 0; ni < 4; ni++) {
            const int colL = nw + ni * 8 + 2 * q;
            const float bx = sBias[colL], by = sBias[colL + 1];
            const size_t r1 = (size_t)mt * BM + mw + mi * 16 + g;
            float* p = out + r1 * D_MODEL + n0 + colL;
            float2 lo = __half22float2(*(__half2*)&d[mi][ni][0]);
            float2 hi = __half22float2(*(__half2*)&d[mi][ni][1]);
            float2 v0 = { lo.x + bx, lo.y + by };
            float2 v1 = { hi.x + bx, hi.y + by };
            *(float2*)p = v0;
            *(float2*)(p + 8 * D_MODEL) = v1;
        }
    }
}

// ---------------------------------------------------------------------------
extern "C" void kernel_launch(void* const* d_in, const int* in_sizes, int n_in,
                              void* d_out, int out_size) {
    const float* x = nullptr; const float* Wg = nullptr; const float* bias = nullptr;
    for (int i = 0; i < n_in; i++) {
        if (in_sizes[i] == BATCH * SEQ * C_IN)   x    = (const float*)d_in[i];
        else if (in_sizes[i] == D_MODEL * KDIM)  Wg   = (const float*)d_in[i];
        else if (in_sizes[i] == D_MODEL)         bias = (const float*)d_in[i];
        // x_mark (BATCH*SEQ*4) unused by the reference math
    }
    float* out = (float*)d_out;

    cudaFuncSetAttribute(stats_kernel, cudaFuncAttributeMaxDynamicSharedMemorySize, S1_SMEM);
    dim3 g1(WPREP_BLOCKS, BATCH + 1);
    stats_kernel<<<g1, P1_TS, S1_SMEM>>>(x, Wg);

    cudaFuncSetAttribute(mma_kernel, cudaFuncAttributeMaxDynamicSharedMemorySize, SMEMB);
    dim3 g2((BATCH * SEQ) / BM, D_MODEL / BN, 1);
    mma_kernel<<<g2, CTH, SMEMB>>>(bias, out);
}